// round 5
// baseline (speedup 1.0000x reference)
#include <cuda_runtime.h>
#include <math.h>

#define VOCABC 1400
#define NVEC   350      // float4 per disease row (1400/4)
#define EPSF   1e-6f
#define MAXN   4096     // survival rows
#define IGRP   8        // i's per concordance block
#define CTHREADS 128

// slotted accumulators: 128B stride -> each slot on its own L2 line
#define NSLOT  32
#define SSTRIDE 32
#define M_DIS  0
#define M_DCNT 1
#define M_TIME 2
#define M_RISK 3
#define M_RCNT 4
#define M_UNC  5
#define M_CONC 6
#define M_PAIR 7
#define NMET   8

// zero at module load; the finalizing block resets after reading, so every
// execution (correctness run + each graph replay) starts from zeros.
__device__ float        g_acc[NMET][NSLOT * SSTRIDE];
__device__ float2       g_tm[MAXN];        // packed (time_target, row_mean)
__device__ unsigned int g_done;
__device__ unsigned int g_mcount;

__device__ __forceinline__ void slot_add(int metric, int slot, float v) {
    atomicAdd(&g_acc[metric][slot * SSTRIDE], v);
}

__device__ __forceinline__ float warp_sum(float v) {
    #pragma unroll
    for (int o = 16; o > 0; o >>= 1) v += __shfl_xor_sync(0xffffffff, v, o);
    return v;
}
__device__ __forceinline__ float warp_max(float v) {
    #pragma unroll
    for (int o = 16; o > 0; o >>= 1) v = fmaxf(v, __shfl_xor_sync(0xffffffff, v, o));
    return v;
}

// =================== fat kernel: CE blocks + concordance blocks =============
__global__ void __launch_bounds__(128) fused_kernel(
        const float* __restrict__ logits, const int* __restrict__ targets,
        const float* __restrict__ tte, const float* __restrict__ ttgt,
        const float* __restrict__ risk, const int* __restrict__ rtgt,
        const float* __restrict__ unc,
        const float* __restrict__ curves, int n_surv, int T,
        const float* __restrict__ ttimes, const int* __restrict__ events,
        int n_tok, float* __restrict__ out) {
    int t = threadIdx.x;

    if (blockIdx.x < (unsigned)n_tok) {
        // ------------------------- CE path ---------------------------------
        int row  = blockIdx.x;
        int slot = row & (NSLOT - 1);
        const float4* base = reinterpret_cast<const float4*>(logits) + (size_t)row * NVEC;

        float4 v0 = base[t];
        float4 v1 = base[t + 128];
        bool   h2 = (t + 256) < NVEC;
        float4 v2 = h2 ? base[t + 256]
                       : make_float4(-INFINITY, -INFINITY, -INFINITY, -INFINITY);

        // fused survival row mean: warp 1 handles row < n_surv
        if (row < n_surv && t >= 32 && t < 64) {
            int lane = t - 32;
            const float* crow = curves + (size_t)row * T;
            float s = 0.f;
            for (int k = lane; k < T; k += 32) s += crow[k];
            #pragma unroll
            for (int o = 16; o > 0; o >>= 1) s += __shfl_xor_sync(0xffffffff, s, o, 32);
            if (lane == 0) {
                g_tm[row] = make_float2(ttimes[row], s / (float)T);
                __threadfence();
                atomicAdd(&g_mcount, 1u);
            }
        }

        // fused per-token scalar losses (idle-lane work)
        if (t == 96) {
            float x    = tte[row];
            float rate = 1.0f / (x + EPSF);
            float tl   = __logf(rate + EPSF) - rate * ttgt[row];
            slot_add(M_TIME, slot, tl);
            slot_add(M_UNC,  slot, unc[row]);
        } else if (t == 64) {
            int r = rtgt[row];
            if (r >= 0) {
                const float* rl = risk + (size_t)row * 5;
                float a0 = rl[0], a1 = rl[1], a2 = rl[2], a3 = rl[3], a4 = rl[4];
                float mm = fmaxf(fmaxf(fmaxf(a0, a1), fmaxf(a2, a3)), a4);
                float ss = __expf(a0 - mm) + __expf(a1 - mm) + __expf(a2 - mm)
                         + __expf(a3 - mm) + __expf(a4 - mm);
                float xt = (r == 0) ? a0 : (r == 1) ? a1 : (r == 2) ? a2 : (r == 3) ? a3 : a4;
                slot_add(M_RISK, slot, -(xt - mm - __logf(ss)));
                slot_add(M_RCNT, slot, 1.0f);
            }
        }

        float m = fmaxf(fmaxf(fmaxf(v0.x, v0.y), fmaxf(v0.z, v0.w)),
                        fmaxf(fmaxf(v1.x, v1.y), fmaxf(v1.z, v1.w)));
        m = fmaxf(m, fmaxf(fmaxf(v2.x, v2.y), fmaxf(v2.z, v2.w)));

        __shared__ float sred[4];
        __shared__ float s_tval;

        int tgt = targets[row];
        if (tgt >= 0) {
            int vi = tgt >> 2;
            if ((vi & 127) == t) {
                float4 v = (vi < 128) ? v0 : ((vi < 256) ? v1 : v2);
                int l = tgt & 3;
                s_tval = (l == 0) ? v.x : (l == 1) ? v.y : (l == 2) ? v.z : v.w;
            }
        }

        m = warp_max(m);
        int warp = t >> 5;
        if ((t & 31) == 0) sred[warp] = m;
        __syncthreads();
        m = fmaxf(fmaxf(sred[0], sred[1]), fmaxf(sred[2], sred[3]));

        float s = __expf(v0.x - m) + __expf(v0.y - m) + __expf(v0.z - m) + __expf(v0.w - m)
                + __expf(v1.x - m) + __expf(v1.y - m) + __expf(v1.z - m) + __expf(v1.w - m);
        if (h2)
            s += __expf(v2.x - m) + __expf(v2.y - m) + __expf(v2.z - m) + __expf(v2.w - m);

        s = warp_sum(s);
        __syncthreads();
        if ((t & 31) == 0) sred[warp] = s;
        __syncthreads();

        if (t == 0 && tgt >= 0) {
            float S   = sred[0] + sred[1] + sred[2] + sred[3];
            float nll = -(s_tval - m - __logf(S));
            slot_add(M_DIS,  slot, nll);
            slot_add(M_DCNT, slot, 1.0f);
        }
    } else {
        // ---------------------- concordance path ---------------------------
        int cb = blockIdx.x - n_tok;       // 0 .. n/IGRP-1
        int i0 = cb * IGRP;
        int n  = n_surv;

        __shared__ int sev[IGRP];
        if (t < IGRP) sev[t] = (i0 + t < n) ? events[i0 + t] : 0;

        // wait for all row means (CE blocks have lower IDs -> no deadlock)
        if (t == 0) {
            volatile unsigned int* mc = &g_mcount;
            while (*mc < (unsigned)n) __nanosleep(64);
        }
        __syncthreads();
        __threadfence();

        float ti[IGRP], mi[IGRP];
        bool  ev[IGRP];
        #pragma unroll
        for (int k = 0; k < IGRP; k++) {
            float2 v = g_tm[i0 + k];       // L2 broadcast
            ti[k] = v.x; mi[k] = v.y;
            ev[k] = (sev[k] == 1);
        }

        float conc = 0.f, cnt = 0.f;

        // peel j in (i0, i0+IGRP): needs j > i0+k predicate
        if (t < IGRP - 1) {
            int j = i0 + 1 + t;
            if (j < n) {
                float2 jm = g_tm[j];
                for (int k = 0; k < j - i0; k++) {
                    if (ev[k] && ti[k] < jm.x) {
                        cnt  += 1.0f;
                        conc += (mi[k] < jm.y) ? 1.0f : ((mi[k] == jm.y) ? 0.5f : 0.0f);
                    }
                }
            }
        }

        // main sweep: j >= i0+IGRP, all k valid (modulo ev / time predicate)
        for (int j = i0 + IGRP + t; j < n; j += CTHREADS) {
            float2 jm = g_tm[j];
            float tj = jm.x, mj = jm.y;
            #pragma unroll
            for (int k = 0; k < IGRP; k++) {
                if (ev[k] && ti[k] < tj) {
                    cnt  += 1.0f;
                    conc += (mi[k] < mj) ? 1.0f : ((mi[k] == mj) ? 0.5f : 0.0f);
                }
            }
        }

        conc = warp_sum(conc);
        cnt  = warp_sum(cnt);
        __shared__ float sc_[4], si_[4];
        int warp = t >> 5;
        if ((t & 31) == 0) { sc_[warp] = conc; si_[warp] = cnt; }
        __syncthreads();
        if (t == 0) {
            float C = sc_[0] + sc_[1] + sc_[2] + sc_[3];
            float P = si_[0] + si_[1] + si_[2] + si_[3];
            if (P > 0.f) {
                int slot = cb & (NSLOT - 1);
                slot_add(M_CONC, slot, C);
                slot_add(M_PAIR, slot, P);
            }
        }
    }

    // ---------------- last-done block (any path) finalizes + resets ---------
    __shared__ bool amLast;
    if (t == 0) {
        __threadfence();
        unsigned v = atomicAdd(&g_done, 1u);
        amLast = (v == gridDim.x - 1);
    }
    __syncthreads();
    if (!amLast) return;

    __shared__ float tot[NMET];
    if (t < NMET) {
        float s = 0.f;
        #pragma unroll
        for (int k = 0; k < NSLOT; k++) s += g_acc[t][k * SSTRIDE];
        tot[t] = s;
    }
    __syncthreads();
    if (t == 0) {
        float dcnt    = tot[M_DCNT] > 0.f ? tot[M_DCNT] : 1.f;
        float rcnt    = tot[M_RCNT] > 0.f ? tot[M_RCNT] : 1.f;
        float disease = tot[M_DIS] / dcnt;
        float timel   = -tot[M_TIME] / (float)n_tok;
        float riskl   = tot[M_RISK] / rcnt;
        float surv    = (tot[M_PAIR] > 0.f) ? 1.0f - tot[M_CONC] / tot[M_PAIR] : 0.0f;
        float u       = (tot[M_UNC] / (float)n_tok) * 0.01f;
        out[0] = disease;
        out[1] = timel;
        out[2] = riskl;
        out[3] = surv;
        out[4] = u;
        out[5] = disease + timel + riskl + surv + u;
        g_done   = 0u;
        g_mcount = 0u;
    }
    // reset accumulators (128 threads; NMET*NSLOT = 256 entries -> 2 per thread)
    #pragma unroll
    for (int e = t; e < NMET * NSLOT; e += 128) {
        int mtr = e / NSLOT, s = e % NSLOT;
        g_acc[mtr][s * SSTRIDE] = 0.f;
    }
}

// ---------------- launch ----------------
extern "C" void kernel_launch(void* const* d_in, const int* in_sizes, int n_in,
                              void* d_out, int out_size) {
    const float* disease_logits = (const float*)d_in[0];
    const int*   disease_tgt    = (const int*)d_in[1];
    const float* tte            = (const float*)d_in[2];
    const float* ttgt           = (const float*)d_in[3];
    const float* risk           = (const float*)d_in[4];
    const int*   risk_tgt       = (const int*)d_in[5];
    const float* curves         = (const float*)d_in[6];
    const float* surv_tgt       = (const float*)d_in[7];
    const int*   events         = (const int*)d_in[8];
    const float* unc            = (const float*)d_in[9];
    float*       out            = (float*)d_out;

    int n_tok = in_sizes[1];            // 16384
    int n     = in_sizes[7];            // 4096
    int T     = in_sizes[6] / n;        // 120

    int conc_blocks = (n + IGRP - 1) / IGRP;   // 512
    fused_kernel<<<n_tok + conc_blocks, 128>>>(
        disease_logits, disease_tgt, tte, ttgt, risk, risk_tgt, unc,
        curves, n, T, surv_tgt, events, n_tok, out);
}